// round 6
// baseline (speedup 1.0000x reference)
#include <cuda_runtime.h>
#include <cstdint>

// Problem constants
#define BATCH  256
#define DI     5120
#define RNK    160
#define NS     16
#define NC     192          // 160 (W_delta) + 16 (W_B) + 16 (W_C) concatenated
#define KSPLIT 32
#define KCHUNK 160          // 5120 / 32

// Scratch (device globals: no allocations allowed)
__device__ float g_Ppart[KSPLIT * BATCH * NC];   // split-K partials for GEMM1
__device__ float g_P[BATCH * NC];                // reduced: [xd | Bp | C] per batch row
__device__ float g_negA[DI * NS];                // -exp(A_log)
__device__ float g_dt[BATCH * DI];               // softplus(xd @ W_dt + b_dt)

// Packed dual-FMA: acc.f32x2 += a.f32x2 * b.f32x2 (exact fp32 FMA per lane)
__device__ __forceinline__ void ffma2(uint64_t& acc, uint64_t a, uint64_t b) {
    asm("fma.rn.f32x2 %0, %1, %2, %0;" : "+l"(acc) : "l"(a), "l"(b));
}
__device__ __forceinline__ float lo32(uint64_t v) { return __uint_as_float((unsigned)(v & 0xffffffffull)); }
__device__ __forceinline__ float hi32(uint64_t v) { return __uint_as_float((unsigned)(v >> 32)); }

// ---------------------------------------------------------------------------
// K1: GEMM1  P_part = X(256x5120) @ [W_delta | W_B | W_C] (5120x192), split-K.
// grid = (3 n-tiles, 4 m-tiles, 32 k-splits), block = 256 threads,
// tile 64x64, TK=32, per-thread 4m x 4n register tile as 4x2 f32x2 pairs.
// X values stored DUPLICATED in shared (float2{v,v}) so the packed broadcast
// operand is a single LDS.64 — no pack-MOVs in the inner loop.
// ---------------------------------------------------------------------------
__global__ __launch_bounds__(256)
void k1_gemm1(const float* __restrict__ X,
              const float* __restrict__ Wd,
              const float* __restrict__ WB,
              const float* __restrict__ WC)
{
    __shared__ float2 Xs2[64][32];   // [m][k], each entry duplicated (v,v): 16 KB
    __shared__ float  Ws[32][64];    // [k][n]: 8 KB

    const int n0 = blockIdx.x * 64;
    const int m0 = blockIdx.y * 64;
    const int k0 = blockIdx.z * KCHUNK;
    const int tid = threadIdx.x;
    const int tx = tid & 15;       // n / 4
    const int ty = tid >> 4;       // m / 4

    uint64_t acc[4][2] = {};       // 0ull == (0.0f, 0.0f)

    const int lk  = tid & 31;      // X load: k within tile
    const int lm  = tid >> 5;      // X load: m base (0..7)
    const int lj  = tid & 63;      // W load: n within tile
    const int lk4 = tid >> 6;      // W load: k base (0..3)
    const int jg  = n0 + lj;       // global concat-column

    for (int kt = 0; kt < KCHUNK; kt += 32) {
        // Load X tile 64x32 (coalesced along k), store duplicated
        #pragma unroll
        for (int i = 0; i < 8; i++) {
            int m = i * 8 + lm;
            float v = X[(size_t)(m0 + m) * DI + (k0 + kt + lk)];
            Xs2[m][lk] = make_float2(v, v);
        }
        // Load W tile 32x64 from the concatenated [W_delta | W_B | W_C]
        #pragma unroll
        for (int i = 0; i < 8; i++) {
            int k  = i * 4 + lk4;
            int kg = k0 + kt + k;
            float w;
            if (jg < 160)       w = Wd[(size_t)kg * 160 + jg];
            else if (jg < 176)  w = WB[(size_t)kg * 16 + (jg - 160)];
            else                w = WC[(size_t)kg * 16 + (jg - 176)];
            Ws[k][lj] = w;
        }
        __syncthreads();

        #pragma unroll
        for (int kk = 0; kk < 32; kk++) {
            ulonglong2 w = *(const ulonglong2*)&Ws[kk][tx * 4];  // (n0n1, n2n3)
            uint64_t a0 = *(const uint64_t*)&Xs2[ty * 4 + 0][kk];
            uint64_t a1 = *(const uint64_t*)&Xs2[ty * 4 + 1][kk];
            uint64_t a2 = *(const uint64_t*)&Xs2[ty * 4 + 2][kk];
            uint64_t a3 = *(const uint64_t*)&Xs2[ty * 4 + 3][kk];
            ffma2(acc[0][0], a0, w.x); ffma2(acc[0][1], a0, w.y);
            ffma2(acc[1][0], a1, w.x); ffma2(acc[1][1], a1, w.y);
            ffma2(acc[2][0], a2, w.x); ffma2(acc[2][1], a2, w.y);
            ffma2(acc[3][0], a3, w.x); ffma2(acc[3][1], a3, w.y);
        }
        __syncthreads();
    }

    float* out = g_Ppart + (size_t)blockIdx.z * (BATCH * NC);
    #pragma unroll
    for (int i = 0; i < 4; i++) {
        size_t row = (size_t)(m0 + ty * 4 + i) * NC + (n0 + tx * 4);
        *(float2*)&out[row + 0] = make_float2(lo32(acc[i][0]), hi32(acc[i][0]));
        *(float2*)&out[row + 2] = make_float2(lo32(acc[i][1]), hi32(acc[i][1]));
    }
}

// ---------------------------------------------------------------------------
// K1b: reduce split-K partials -> g_P, and precompute g_negA = -exp(A_log).
// ---------------------------------------------------------------------------
__global__ __launch_bounds__(256)
void k1b_reduce(const float* __restrict__ A_log)
{
    int i = blockIdx.x * 256 + threadIdx.x;
    if (i < BATCH * NC) {
        float s = 0.f;
        #pragma unroll
        for (int p = 0; p < KSPLIT; p++)
            s += g_Ppart[(size_t)p * (BATCH * NC) + i];
        g_P[i] = s;
    }
    if (i < DI * NS)
        g_negA[i] = -__expf(A_log[i]);
}

// ---------------------------------------------------------------------------
// K2: GEMM2  dt = softplus(xd(256x160) @ W_dt(160x5120) + b_dt).
// grid = (80 n-tiles, 8 m-tiles), block = 256, tile 32x64, TK=32,
// per-thread 2m x 4n register tile as 2x2 f32x2 pairs. Same dup-X trick.
// ---------------------------------------------------------------------------
__global__ __launch_bounds__(256)
void k2_gemm2(const float* __restrict__ Wdt,
              const float* __restrict__ bdt)
{
    __shared__ float2 Xs2[32][32];  // [m(b)][k(r)], duplicated: 8 KB
    __shared__ float  Ws[32][64];   // [k(r)][n(d)]: 8 KB

    const int n0 = blockIdx.x * 64;
    const int m0 = blockIdx.y * 32;
    const int tid = threadIdx.x;
    const int tx = tid & 15;       // n / 4
    const int ty = tid >> 4;       // m / 2 (0..15)

    uint64_t acc[2][2] = {};

    const int lk  = tid & 31;
    const int lm  = tid >> 5;      // 0..7
    const int lj  = tid & 63;
    const int lk4 = tid >> 6;      // 0..3

    for (int kt = 0; kt < RNK; kt += 32) {
        // X tile 32x32 from g_P (xd = first 160 columns, row stride NC)
        #pragma unroll
        for (int i = 0; i < 4; i++) {
            int m = i * 8 + lm;
            float v = g_P[(size_t)(m0 + m) * NC + (kt + lk)];
            Xs2[m][lk] = make_float2(v, v);
        }
        // W tile 32x64 from W_dt (row-major 160 x 5120)
        #pragma unroll
        for (int i = 0; i < 8; i++) {
            int k = i * 4 + lk4;
            Ws[k][lj] = Wdt[(size_t)(kt + k) * DI + (n0 + lj)];
        }
        __syncthreads();

        #pragma unroll
        for (int kk = 0; kk < 32; kk++) {
            ulonglong2 w = *(const ulonglong2*)&Ws[kk][tx * 4];
            uint64_t a0 = *(const uint64_t*)&Xs2[ty * 2 + 0][kk];
            uint64_t a1 = *(const uint64_t*)&Xs2[ty * 2 + 1][kk];
            ffma2(acc[0][0], a0, w.x); ffma2(acc[0][1], a0, w.y);
            ffma2(acc[1][0], a1, w.x); ffma2(acc[1][1], a1, w.y);
        }
        __syncthreads();
    }

    #pragma unroll
    for (int i = 0; i < 2; i++) {
        float v[4] = { lo32(acc[i][0]), hi32(acc[i][0]),
                       lo32(acc[i][1]), hi32(acc[i][1]) };
        #pragma unroll
        for (int j = 0; j < 4; j++) {
            int dg = n0 + tx * 4 + j;
            float z = v[j] + bdt[dg];
            // softplus with threshold 20 (matches reference)
            float sp = (z > 20.f) ? z : log1pf(__expf(z));
            g_dt[(size_t)(m0 + ty * 2 + i) * DI + dg] = sp;
        }
    }
}

// ---------------------------------------------------------------------------
// K3: fused readout, warp-cooperative coalesced layout.
// 4 lanes per (b,d) row: lane c owns n-chunk [4c, 4c+4). A warp's h/negA
// float4 loads cover 512 contiguous bytes (4 L1 wavefronts = minimum).
// Partial dot over n reduced with 2x shfl_xor. Each block = 256 consecutive
// idx -> b constant per block (DI % 256 == 0); C/Bp staged in shared.
// y[b,d] = sum_n exp(dt*negA[d,n])*h[b,d,n]*C[b,n] + dt*x*(Bp.C) + x*D[d]
// ---------------------------------------------------------------------------
__global__ __launch_bounds__(256)
void k3_main(const float* __restrict__ x,
             const float* __restrict__ h,
             const float* __restrict__ Dv,
             float* __restrict__ y)
{
    const int tid  = threadIdx.x;
    const int warp = tid >> 5;
    const int lane = tid & 31;
    const int r = lane >> 2;        // row within 8-row group
    const int c = lane & 3;         // n-chunk
    const int base = blockIdx.x * 256;
    const int b = base / DI;        // constant within block

    __shared__ __align__(16) float sC[16];
    __shared__ __align__(16) float sB[16];
    if (tid < 16)       sC[tid]      = g_P[(size_t)b * NC + 176 + tid];
    else if (tid < 32)  sB[tid - 16] = g_P[(size_t)b * NC + 160 + (tid - 16)];
    __syncthreads();

    const float4 cv = *(const float4*)&sC[c * 4];
    const float4 bv = *(const float4*)&sB[c * 4];
    // bc = Bp . C (full), via 4-lane butterfly
    float bc = fmaf(bv.x, cv.x, fmaf(bv.y, cv.y, fmaf(bv.z, cv.z, bv.w * cv.w)));
    bc += __shfl_xor_sync(0xffffffffu, bc, 1);
    bc += __shfl_xor_sync(0xffffffffu, bc, 2);

    #pragma unroll
    for (int s = 0; s < 4; s++) {
        const int row = base + warp * 32 + s * 8 + r;
        const int d   = row - b * DI;
        const float dt = g_dt[row];
        const float xv = x[row];
        const float4 hv = *(const float4*)(h      + (size_t)row * NS + c * 4);
        const float4 av = *(const float4*)(g_negA + (size_t)d   * NS + c * 4);
        float p;
        p = __expf(dt * av.x) * hv.x * cv.x;
        p = fmaf(__expf(dt * av.y) * hv.y, cv.y, p);
        p = fmaf(__expf(dt * av.z) * hv.z, cv.z, p);
        p = fmaf(__expf(dt * av.w) * hv.w, cv.w, p);
        p += __shfl_xor_sync(0xffffffffu, p, 1);
        p += __shfl_xor_sync(0xffffffffu, p, 2);
        if (c == 0)
            y[row] = p + dt * xv * bc + xv * Dv[d];
    }
}

// ---------------------------------------------------------------------------
// Launch: 4 kernels, stream-ordered, graph-capturable, no allocations,
// no atomics (bitwise deterministic).
// Input order (metadata): x, h, W_delta, W_dt, b_dt, A_log, W_B, W_C, D
// ---------------------------------------------------------------------------
extern "C" void kernel_launch(void* const* d_in, const int* in_sizes, int n_in,
                              void* d_out, int out_size)
{
    const float* x      = (const float*)d_in[0];
    const float* h      = (const float*)d_in[1];
    const float* Wdelta = (const float*)d_in[2];
    const float* Wdt    = (const float*)d_in[3];
    const float* bdt    = (const float*)d_in[4];
    const float* Alog   = (const float*)d_in[5];
    const float* WB     = (const float*)d_in[6];
    const float* WC     = (const float*)d_in[7];
    const float* Dv     = (const float*)d_in[8];
    float* y = (float*)d_out;

    dim3 g1(NC / 64, BATCH / 64, KSPLIT);              // 3 x 4 x 32 = 384 blocks
    k1_gemm1<<<g1, 256>>>(x, Wdelta, WB, WC);

    k1b_reduce<<<(DI * NS + 255) / 256, 256>>>(Alog);  // 320 blocks

    dim3 g2(DI / 64, BATCH / 32);                      // 80 x 8 = 640 blocks
    k2_gemm2<<<g2, 256>>>(Wdt, bdt);

    k3_main<<<(BATCH * DI) / 256, 256>>>(x, h, Dv, y); // 5120 blocks
}

// round 7
// speedup vs baseline: 1.1238x; 1.1238x over previous
#include <cuda_runtime.h>
#include <cstdint>

// Problem constants
#define BATCH  256
#define DI     5120
#define RNK    160
#define NS     16
#define NC     192          // 160 (W_delta) + 16 (W_B) + 16 (W_C) concatenated
#define KSPLIT 40
#define KCHUNK 128          // DI / KSPLIT

// Scratch (device globals: no allocations allowed)
__device__ float g_Ppart[KSPLIT * BATCH * NC];   // split-K partials for GEMM1
__device__ float g_P[BATCH * NC];                // reduced: [xd | Bp | C] per batch row
__device__ float g_negA[DI * NS];                // -exp(A_log)
__device__ float g_dt[BATCH * DI];               // softplus(xd @ W_dt + b_dt)

// ---- packed dual-FMA helpers (FFMA2: 2 fp32 FMAs per instruction) ----
__device__ __forceinline__ void ffma2(uint64_t& acc, uint64_t a, uint64_t b) {
    asm("fma.rn.f32x2 %0, %1, %2, %0;" : "+l"(acc) : "l"(a), "l"(b));
}
__device__ __forceinline__ uint64_t dup2(float v) {
    uint64_t r;
    asm("mov.b64 %0, {%1, %1};" : "=l"(r) : "r"(__float_as_uint(v)));
    return r;
}
__device__ __forceinline__ float lo32(uint64_t v) { return __uint_as_float((unsigned)v); }
__device__ __forceinline__ float hi32(uint64_t v) { return __uint_as_float((unsigned)(v >> 32)); }

// ---- fast exp on the FMA/ALU pipes (no MUFU). |rel err| ~1e-7 on [-87, 0]. ----
__device__ __forceinline__ float fast_expf(float x) {
    x = fmaxf(x, -87.0f);                              // keep 2^i in normal range
    float r  = fmaf(x, 1.442695041f, 12582912.0f);     // t + 1.5*2^23 : rne integer
    float fi = r - 12582912.0f;                        // rounded integer part of t
    int   ib = __float_as_int(r) - 0x4B400000;         // same integer as int
    float f  = fmaf(x, 1.442695041f, -fi);             // frac in [-0.5, 0.5]
    float p  = 1.5403530e-4f;                          // Taylor of 2^f
    p = fmaf(p, f, 1.3333558e-3f);
    p = fmaf(p, f, 9.6181292e-3f);
    p = fmaf(p, f, 5.5504109e-2f);
    p = fmaf(p, f, 2.4022651e-1f);
    p = fmaf(p, f, 6.9314718e-1f);
    p = fmaf(p, f, 1.0f);
    return __int_as_float(__float_as_int(p) + (ib << 23));   // p * 2^i
}

// ---------------------------------------------------------------------------
// K1: GEMM1  P_part = X(256x5120) @ [W_delta | W_B | W_C] (5120x192), split-K.
// grid = (3 n, 4 m, 40 k) = 480 blocks, 256 threads, tile 64x64, TK=32,
// 4 double-buffered stages (register prefetch). X transposed in smem so the
// packed (m,m+1) operand is a single LDS.64; W broadcast via mov.b64 dup.
// Inner loop: 15 instr / 32 FMA.
// ---------------------------------------------------------------------------
__global__ __launch_bounds__(256)
void k1_gemm1(const float* __restrict__ X,
              const float* __restrict__ Wd,
              const float* __restrict__ WB,
              const float* __restrict__ WC)
{
    __shared__ float XsT[32][66];   // [k][m], +2 pad: 8B-aligned rows, low conflict
    __shared__ float Ws[32][64];    // [k][n]

    const int n0 = blockIdx.x * 64;
    const int m0 = blockIdx.y * 64;
    const int k0 = blockIdx.z * KCHUNK;
    const int tid = threadIdx.x;
    const int tx = tid & 15;        // n / 4
    const int ty = tid >> 4;        // m / 4
    const int lk  = tid & 31;       // X loader: k within tile
    const int lm  = tid >> 5;       // X loader: m base (0..7)
    const int lj  = tid & 63;       // W loader: n within tile
    const int lk4 = tid >> 6;       // W loader: k base (0..3)
    const int jg  = n0 + lj;

    const float* Wp; int wstr, wcol;
    if (jg < 160)      { Wp = Wd; wstr = 160; wcol = jg; }
    else if (jg < 176) { Wp = WB; wstr = 16;  wcol = jg - 160; }
    else               { Wp = WC; wstr = 16;  wcol = jg - 176; }

    float px[8], pw[8];
    uint64_t acc[2][4] = {};        // [m-pair][n], packed along m

    auto ldg_stage = [&](int s) {
        const int kb = k0 + s * 32;
        #pragma unroll
        for (int i = 0; i < 8; i++)
            px[i] = X[(size_t)(m0 + i * 8 + lm) * DI + kb + lk];
        #pragma unroll
        for (int i = 0; i < 8; i++)
            pw[i] = Wp[(size_t)(kb + i * 4 + lk4) * wstr + wcol];
    };
    auto sts_stage = [&]() {
        #pragma unroll
        for (int i = 0; i < 8; i++) XsT[lk][i * 8 + lm] = px[i];
        #pragma unroll
        for (int i = 0; i < 8; i++) Ws[i * 4 + lk4][lj] = pw[i];
    };

    ldg_stage(0); sts_stage(); __syncthreads();

    const int NSTG = KCHUNK / 32;   // 4
    #pragma unroll
    for (int s = 0; s < NSTG; s++) {
        if (s + 1 < NSTG) ldg_stage(s + 1);   // LDGs in flight under compute
        #pragma unroll
        for (int kk = 0; kk < 32; kk++) {
            float4 wv = *(const float4*)&Ws[kk][tx * 4];
            uint64_t w0 = dup2(wv.x), w1 = dup2(wv.y), w2 = dup2(wv.z), w3 = dup2(wv.w);
            uint64_t a0 = *(const uint64_t*)&XsT[kk][ty * 4];       // (m, m+1)
            uint64_t a1 = *(const uint64_t*)&XsT[kk][ty * 4 + 2];   // (m+2, m+3)
            ffma2(acc[0][0], a0, w0); ffma2(acc[0][1], a0, w1);
            ffma2(acc[0][2], a0, w2); ffma2(acc[0][3], a0, w3);
            ffma2(acc[1][0], a1, w0); ffma2(acc[1][1], a1, w1);
            ffma2(acc[1][2], a1, w2); ffma2(acc[1][3], a1, w3);
        }
        __syncthreads();
        if (s + 1 < NSTG) { sts_stage(); __syncthreads(); }
    }

    float* out = g_Ppart + (size_t)blockIdx.z * (BATCH * NC);
    #pragma unroll
    for (int p = 0; p < 2; p++)
        #pragma unroll
        for (int j = 0; j < 4; j++) {
            const int n = n0 + tx * 4 + j;
            const int m = m0 + ty * 4 + p * 2;
            out[(size_t)m * NC + n]       = lo32(acc[p][j]);
            out[(size_t)(m + 1) * NC + n] = hi32(acc[p][j]);
        }
}

// ---------------------------------------------------------------------------
// K1b: reduce split-K partials -> g_P, and precompute g_negA = -exp(A_log).
// ---------------------------------------------------------------------------
__global__ __launch_bounds__(256)
void k1b_reduce(const float* __restrict__ A_log)
{
    int i = blockIdx.x * 256 + threadIdx.x;
    if (i < BATCH * NC) {
        float s = 0.f;
        #pragma unroll
        for (int p = 0; p < KSPLIT; p++)
            s += g_Ppart[(size_t)p * (BATCH * NC) + i];
        g_P[i] = s;
    }
    if (i < DI * NS)
        g_negA[i] = -__expf(A_log[i]);
}

// ---------------------------------------------------------------------------
// K2: GEMM2  dt = softplus(xd(256x160) @ W_dt(160x5120) + b_dt).
// grid = (80 n, 8 m) = 640 blocks, tile 32x64, TK=32, 5 double-buffered
// stages, packed-m FFMA2 (10 instr / 16 FMA inner loop).
// ---------------------------------------------------------------------------
__global__ __launch_bounds__(256)
void k2_gemm2(const float* __restrict__ Wdt,
              const float* __restrict__ bdt)
{
    __shared__ float XsT[32][34];   // [k(r)][m(b)], +2 pad
    __shared__ float Ws[32][64];    // [k(r)][n(d)]

    const int n0 = blockIdx.x * 64;
    const int m0 = blockIdx.y * 32;
    const int tid = threadIdx.x;
    const int tx = tid & 15;        // n / 4
    const int ty = tid >> 4;        // m-pair index (0..15) -> rows (2ty, 2ty+1)
    const int lk  = tid & 31;
    const int lm  = tid >> 5;       // 0..7
    const int lj  = tid & 63;
    const int lk4 = tid >> 6;       // 0..3

    float px[4], pw[8];
    uint64_t acc[4] = {};           // packed (m even, m odd) x 4 n

    auto ldg_stage = [&](int s) {
        const int kb = s * 32;
        #pragma unroll
        for (int i = 0; i < 4; i++)
            px[i] = g_P[(size_t)(m0 + i * 8 + lm) * NC + kb + lk];
        #pragma unroll
        for (int i = 0; i < 8; i++)
            pw[i] = Wdt[(size_t)(kb + i * 4 + lk4) * DI + n0 + lj];
    };
    auto sts_stage = [&]() {
        #pragma unroll
        for (int i = 0; i < 4; i++) XsT[lk][i * 8 + lm] = px[i];
        #pragma unroll
        for (int i = 0; i < 8; i++) Ws[i * 4 + lk4][lj] = pw[i];
    };

    ldg_stage(0); sts_stage(); __syncthreads();

    #pragma unroll
    for (int s = 0; s < 5; s++) {
        if (s < 4) ldg_stage(s + 1);
        #pragma unroll
        for (int kk = 0; kk < 32; kk++) {
            float4 wv = *(const float4*)&Ws[kk][tx * 4];
            uint64_t a = *(const uint64_t*)&XsT[kk][ty * 2];
            ffma2(acc[0], a, dup2(wv.x));
            ffma2(acc[1], a, dup2(wv.y));
            ffma2(acc[2], a, dup2(wv.z));
            ffma2(acc[3], a, dup2(wv.w));
        }
        __syncthreads();
        if (s < 4) { sts_stage(); __syncthreads(); }
    }

    #pragma unroll
    for (int j = 0; j < 4; j++) {
        const int dg = n0 + tx * 4 + j;
        const float bias = bdt[dg];
        float z0 = lo32(acc[j]) + bias;
        float z1 = hi32(acc[j]) + bias;
        float s0 = (z0 > 20.f) ? z0 : log1pf(__expf(z0));
        float s1 = (z1 > 20.f) ? z1 : log1pf(__expf(z1));
        g_dt[(size_t)(m0 + ty * 2) * DI + dg]     = s0;
        g_dt[(size_t)(m0 + ty * 2 + 1) * DI + dg] = s1;
    }
}

// ---------------------------------------------------------------------------
// K3: fused readout. Warp-cooperative: 4 lanes per (b,d) row (coalesced h),
// exp computed on FMA/ALU pipes (fast_expf) -> MUFU pipe freed entirely.
// y[b,d] = sum_n exp(dt*negA[d,n])*h[b,d,n]*C[b,n] + dt*x*(Bp.C) + x*D[d]
// ---------------------------------------------------------------------------
__global__ __launch_bounds__(256)
void k3_main(const float* __restrict__ x,
             const float* __restrict__ h,
             const float* __restrict__ Dv,
             float* __restrict__ y)
{
    const int tid  = threadIdx.x;
    const int warp = tid >> 5;
    const int lane = tid & 31;
    const int r = lane >> 2;        // row within 8-row group
    const int c = lane & 3;         // n-chunk
    const int base = blockIdx.x * 256;
    const int b = base / DI;        // constant within block (DI % 256 == 0)

    __shared__ __align__(16) float sC[16];
    __shared__ __align__(16) float sB[16];
    if (tid < 16)       sC[tid]      = g_P[(size_t)b * NC + 176 + tid];
    else if (tid < 32)  sB[tid - 16] = g_P[(size_t)b * NC + 160 + (tid - 16)];
    __syncthreads();

    const float4 cv = *(const float4*)&sC[c * 4];
    const float4 bv = *(const float4*)&sB[c * 4];
    float bc = fmaf(bv.x, cv.x, fmaf(bv.y, cv.y, fmaf(bv.z, cv.z, bv.w * cv.w)));
    bc += __shfl_xor_sync(0xffffffffu, bc, 1);
    bc += __shfl_xor_sync(0xffffffffu, bc, 2);

    #pragma unroll
    for (int s = 0; s < 4; s++) {
        const int row = base + warp * 32 + s * 8 + r;
        const int d   = row - b * DI;
        const float dt = g_dt[row];
        const float xv = x[row];
        const float4 hv = *(const float4*)(h      + (size_t)row * NS + c * 4);
        const float4 av = *(const float4*)(g_negA + (size_t)d   * NS + c * 4);
        float p;
        p = fast_expf(dt * av.x) * hv.x * cv.x;
        p = fmaf(fast_expf(dt * av.y) * hv.y, cv.y, p);
        p = fmaf(fast_expf(dt * av.z) * hv.z, cv.z, p);
        p = fmaf(fast_expf(dt * av.w) * hv.w, cv.w, p);
        p += __shfl_xor_sync(0xffffffffu, p, 1);
        p += __shfl_xor_sync(0xffffffffu, p, 2);
        if (c == 0)
            y[row] = p + dt * xv * bc + xv * Dv[d];
    }
}

// ---------------------------------------------------------------------------
// Launch: 4 kernels, stream-ordered, graph-capturable, no allocations,
// no atomics (bitwise deterministic).
// Input order (metadata): x, h, W_delta, W_dt, b_dt, A_log, W_B, W_C, D
// ---------------------------------------------------------------------------
extern "C" void kernel_launch(void* const* d_in, const int* in_sizes, int n_in,
                              void* d_out, int out_size)
{
    const float* x      = (const float*)d_in[0];
    const float* h      = (const float*)d_in[1];
    const float* Wdelta = (const float*)d_in[2];
    const float* Wdt    = (const float*)d_in[3];
    const float* bdt    = (const float*)d_in[4];
    const float* Alog   = (const float*)d_in[5];
    const float* WB     = (const float*)d_in[6];
    const float* WC     = (const float*)d_in[7];
    const float* Dv     = (const float*)d_in[8];
    float* y = (float*)d_out;

    dim3 g1(NC / 64, BATCH / 64, KSPLIT);              // 3 x 4 x 40 = 480 blocks
    k1_gemm1<<<g1, 256>>>(x, Wdelta, WB, WC);

    k1b_reduce<<<(DI * NS + 255) / 256, 256>>>(Alog);  // 320 blocks

    dim3 g2(DI / 64, BATCH / 32);                      // 80 x 8 = 640 blocks
    k2_gemm2<<<g2, 256>>>(Wdt, bdt);

    k3_main<<<(BATCH * DI) / 256, 256>>>(x, h, Dv, y); // 5120 blocks
}